// round 12
// baseline (speedup 1.0000x reference)
#include <cuda_runtime.h>
#include <cstdint>
#include <math.h>

// ---------------- problem constants ----------------
#define TT    12
#define NITER 10
#define CANDS 1000
#define KTOP  100
#define AD    6
#define BBATCH 16
#define HD    200
#define ZD    30
#define NTOT  (BBATCH * CANDS)     // 16000
#define NELEM (TT * NTOT * AD)     // 1152000
#define CPW   5                    // candidates per warp
#define MBLK  (8 * CPW)            // 40 candidates per block
#define NBLK  (NTOT / MBLK)        // 400 exactly; <= 3*148 -> one wave at 3 CTAs/SM

typedef unsigned long long ull;

// ---------------- device scratch (no allocations allowed) ----------------
__device__ float g_actions[NELEM];          // [T][16000][6]
__device__ float g_returns[NTOT];
__device__ float g_mean[TT * BBATCH * AD];  // [T][B][A]
__device__ float g_std [TT * BBATCH * AD];

// packed weights (prep_kernel fills once per launch)
// per k, per lane: two 16B quads:
//   quad j=0: ( pair(h0,h0+32), pair(h1,h1+32) )
//   quad j=1: ( pair(h2,h2+32), (w6, 0) )        h_q = lane + 64q, w6 = W[k][192+lane] (lane<8)
__device__ ulonglong2 g_WbQ[200 * 2 * 32];
__device__ ulonglong2 g_WsQ[ 30 * 2 * 32];
__device__ ulonglong2 g_WaQ[  6 * 2 * 32];
__device__ ull        g_Wzp[100 * 32];      // (Wz[2k2][z], Wz[2k2+1][z]), 0 if z>=30

// ---------------- f32x2 helpers ----------------
__device__ __forceinline__ ull pk2(float a, float b) {
    ull r; asm("mov.b64 %0, {%1, %2};" : "=l"(r) : "f"(a), "f"(b)); return r;
}
__device__ __forceinline__ void upk2(float& a, float& b, ull v) {
    asm("mov.b64 {%0, %1}, %2;" : "=f"(a), "=f"(b) : "l"(v));
}
__device__ __forceinline__ void fma2(ull& d, ull a, ull b) {
    asm("fma.rn.f32x2 %0, %1, %2, %3;" : "=l"(d) : "l"(a), "l"(b), "l"(d));
}

// fast exact-identity tanh: 1 - 2/(e^{2x}+1); abs err ~1e-7, no NaN at +/-inf
__device__ __forceinline__ float tanh_fast(float x) {
    float e = __expf(2.0f * x);
    return 1.0f - __fdividef(2.0f, e + 1.0f);
}

// ---------------- Threefry-2x32-20 (exactly JAX's) ----------------
__host__ __device__ inline unsigned rotl32(unsigned v, int d) {
    return (v << d) | (v >> (32 - d));
}

__host__ __device__ inline void tf2x32(unsigned k0, unsigned k1,
                                       unsigned x0, unsigned x1,
                                       unsigned& o0, unsigned& o1) {
    unsigned ks0 = k0, ks1 = k1, ks2 = k0 ^ k1 ^ 0x1BD11BDAu;
    x0 += ks0; x1 += ks1;
#define TF_RND(r) { x0 += x1; x1 = rotl32(x1, (r)); x1 ^= x0; }
    TF_RND(13) TF_RND(15) TF_RND(26) TF_RND(6)
    x0 += ks1; x1 += ks2 + 1u;
    TF_RND(17) TF_RND(29) TF_RND(16) TF_RND(24)
    x0 += ks2; x1 += ks0 + 2u;
    TF_RND(13) TF_RND(15) TF_RND(26) TF_RND(6)
    x0 += ks0; x1 += ks1 + 3u;
    TF_RND(17) TF_RND(29) TF_RND(16) TF_RND(24)
    x0 += ks1; x1 += ks2 + 4u;
    TF_RND(13) TF_RND(15) TF_RND(26) TF_RND(6)
    x0 += ks2; x1 += ks0 + 5u;
#undef TF_RND
    o0 = x0; o1 = x1;
}

// XLA's f32 erf_inv (Giles polynomial), matching lax.erf_inv on GPU.
__device__ inline float xla_erfinvf(float x) {
    float w = -log1pf(-x * x);
    float p;
    if (w < 5.0f) {
        w -= 2.5f;
        p = 2.81022636e-08f;
        p = fmaf(p, w, 3.43273939e-07f);
        p = fmaf(p, w, -3.5233877e-06f);
        p = fmaf(p, w, -4.39150654e-06f);
        p = fmaf(p, w, 0.00021858087f);
        p = fmaf(p, w, -0.00125372503f);
        p = fmaf(p, w, -0.00417768164f);
        p = fmaf(p, w, 0.246640727f);
        p = fmaf(p, w, 1.50140941f);
    } else {
        w = sqrtf(w) - 3.0f;
        p = -0.000200214257f;
        p = fmaf(p, w, 0.000100950558f);
        p = fmaf(p, w, 0.00134934322f);
        p = fmaf(p, w, -0.00367342844f);
        p = fmaf(p, w, 0.00573950773f);
        p = fmaf(p, w, -0.0076224613f);
        p = fmaf(p, w, 0.00943887047f);
        p = fmaf(p, w, 1.00167406f);
        p = fmaf(p, w, 2.83297682f);
    }
    return p * x;
}

// bits -> uniform in [lo, 1) (JAX semantics) -> standard normal via erfinv
__device__ inline float bits_to_normal(unsigned bits) {
    float f = __uint_as_float((bits >> 9) | 0x3F800000u) - 1.0f;  // [0,1), exact
    float u = fmaf(f, 2.0f, -0.99999994f);
    u = fmaxf(-0.99999994f, u);
    return 1.41421356237f * xla_erfinvf(u);
}

// ---------------- kernels ----------------
__global__ void init_ms_kernel() {
    int i = blockIdx.x * blockDim.x + threadIdx.x;
    if (i < TT * BBATCH * AD) { g_mean[i] = 0.0f; g_std[i] = 1.0f; }
}

// Build packed/interleaved weight arrays. One thread per (k,lane) slot.
__global__ void prep_kernel(const float* __restrict__ Wb, const float* __restrict__ Ws,
                            const float* __restrict__ Wa, const float* __restrict__ Wz)
{
    int i = blockIdx.x * blockDim.x + threadIdx.x;
    if (i < 200 * 32) {
        int k = i >> 5, lane = i & 31;
        int h0 = lane, h1 = lane + 64, h2 = lane + 128;
        float w6 = (lane < 8) ? Wb[k * HD + 192 + lane] : 0.0f;
        g_WbQ[(k * 2 + 0) * 32 + lane] = make_ulonglong2(
            pk2(Wb[k * HD + h0], Wb[k * HD + h0 + 32]),
            pk2(Wb[k * HD + h1], Wb[k * HD + h1 + 32]));
        g_WbQ[(k * 2 + 1) * 32 + lane] = make_ulonglong2(
            pk2(Wb[k * HD + h2], Wb[k * HD + h2 + 32]),
            pk2(w6, 0.0f));
    }
    int j = i - 200 * 32;
    if (j >= 0 && j < 30 * 32) {
        int k = j >> 5, lane = j & 31;
        int h0 = lane, h1 = lane + 64, h2 = lane + 128;
        float w6 = (lane < 8) ? Ws[k * HD + 192 + lane] : 0.0f;
        g_WsQ[(k * 2 + 0) * 32 + lane] = make_ulonglong2(
            pk2(Ws[k * HD + h0], Ws[k * HD + h0 + 32]),
            pk2(Ws[k * HD + h1], Ws[k * HD + h1 + 32]));
        g_WsQ[(k * 2 + 1) * 32 + lane] = make_ulonglong2(
            pk2(Ws[k * HD + h2], Ws[k * HD + h2 + 32]),
            pk2(w6, 0.0f));
    }
    int l = j - 30 * 32;
    if (l >= 0 && l < 6 * 32) {
        int k = l >> 5, lane = l & 31;
        int h0 = lane, h1 = lane + 64, h2 = lane + 128;
        float w6 = (lane < 8) ? Wa[k * HD + 192 + lane] : 0.0f;
        g_WaQ[(k * 2 + 0) * 32 + lane] = make_ulonglong2(
            pk2(Wa[k * HD + h0], Wa[k * HD + h0 + 32]),
            pk2(Wa[k * HD + h1], Wa[k * HD + h1 + 32]));
        g_WaQ[(k * 2 + 1) * 32 + lane] = make_ulonglong2(
            pk2(Wa[k * HD + h2], Wa[k * HD + h2 + 32]),
            pk2(w6, 0.0f));
    }
    int m = l - 6 * 32;
    if (m >= 0 && m < 100 * 32) {
        int k2 = m >> 5, z = m & 31;
        float e = (z < ZD) ? Wz[(2 * k2) * ZD + z] : 0.0f;
        float o = (z < ZD) ? Wz[(2 * k2 + 1) * ZD + z] : 0.0f;
        g_Wzp[m] = pk2(e, o);
    }
}

// Partitionable threefry, 32-bit output: bits[i] = o0 ^ o1 of
// threefry(key, counter=(hi=0, lo=i))
__global__ void gen_kernel(unsigned k0, unsigned k1) {
    int i = blockIdx.x * blockDim.x + threadIdx.x;
    if (i >= NELEM) return;
    unsigned o0, o1;
    tf2x32(k0, k1, 0u, (unsigned)i, o0, o1);
    float z = bits_to_normal(o0 ^ o1);
    int ms = (i / (CANDS * AD)) * AD + (i % AD);  // (t*B+b)*A + a
    g_actions[i] = fmaf(g_std[ms], z, g_mean[ms]);
}

// Fused 12-step rollout, f32x2-packed, LDG.128 weights, fast tanh.
// 3 CTAs/SM via CPW=5; beliefs in smem (warp-private rows);
// states/actions lane-distributed in registers.
// lane covers h-columns: pairs (lane+64q, lane+64q+32) q=0..2 + scalar 192+lane (lane<8)
__global__ __launch_bounds__(256, 3)
void rollout_kernel(const float* __restrict__ belief, const float* __restrict__ state,
                    const float* __restrict__ bbv, const float* __restrict__ bzv,
                    const float* __restrict__ Wr, const float* __restrict__ brv)
{
    __shared__ __align__(16) float sb[MBLK * HD];   // 32000 B static

    const int tid  = threadIdx.x;
    const int lane = tid & 31;
    const int warp = tid >> 5;
    const int nb   = blockIdx.x * MBLK + warp * CPW;   // first candidate of this warp

    // cooperative initial belief load (NBLK*MBLK == NTOT exactly; no clamps)
    for (int i = tid; i < MBLK * HD; i += 256) {
        int m = i / HD, h = i - m * HD;
        sb[i] = belief[((blockIdx.x * MBLK + m) / CANDS) * HD + h];
    }

    float sreg[CPW];   // lane z (<30) holds s[cand][z]
#pragma unroll
    for (int i = 0; i < CPW; ++i)
        sreg[i] = (lane < ZD) ? state[((nb + i) / CANDS) * ZD + lane] : 0.0f;

    const bool  t6v  = (lane < 8);
    const bool  zval = (lane < ZD);
    const float bzz  = zval ? __ldg(&bzv[lane]) : 0.0f;

    float rp[CPW];
#pragma unroll
    for (int i = 0; i < CPW; ++i) rp[i] = 0.0f;

    const int m0 = warp * CPW;
    __syncthreads();   // sb ready (only cross-warp dependency)

    for (int t = 0; t < TT; ++t) {
        ull accp[CPW][4];     // 4th pair = (tail, 0)
#pragma unroll
        for (int i = 0; i < CPW; ++i)
#pragma unroll
            for (int q = 0; q < 4; ++q) accp[i][q] = 0ULL;

        // b @ Wb   (K = 200)
        for (int k2 = 0; k2 < HD / 2; ++k2) {
            float2 bv[CPW];
#pragma unroll
            for (int i = 0; i < CPW; ++i)
                bv[i] = *reinterpret_cast<const float2*>(&sb[(m0 + i) * HD + 2 * k2]);
#pragma unroll
            for (int kk = 0; kk < 2; ++kk) {
                int k = 2 * k2 + kk;
                ulonglong2 w01 = __ldg(&g_WbQ[(k * 2 + 0) * 32 + lane]);
                ulonglong2 w23 = __ldg(&g_WbQ[(k * 2 + 1) * 32 + lane]);
#pragma unroll
                for (int i = 0; i < CPW; ++i) {
                    float bk = kk ? bv[i].y : bv[i].x;
                    ull bk2 = pk2(bk, bk);
                    fma2(accp[i][0], bk2, w01.x);
                    fma2(accp[i][1], bk2, w01.y);
                    fma2(accp[i][2], bk2, w23.x);
                    fma2(accp[i][3], bk2, w23.y);
                }
            }
        }
        // s @ Ws   (K = 30)
        for (int k = 0; k < ZD; ++k) {
            ulonglong2 w01 = __ldg(&g_WsQ[(k * 2 + 0) * 32 + lane]);
            ulonglong2 w23 = __ldg(&g_WsQ[(k * 2 + 1) * 32 + lane]);
#pragma unroll
            for (int i = 0; i < CPW; ++i) {
                float sk = __shfl_sync(0xFFFFFFFFu, sreg[i], k);
                ull sk2 = pk2(sk, sk);
                fma2(accp[i][0], sk2, w01.x);
                fma2(accp[i][1], sk2, w01.y);
                fma2(accp[i][2], sk2, w23.x);
                fma2(accp[i][3], sk2, w23.y);
            }
        }
        // a @ Wa   (K = 6) — actions loaded just-in-time
        {
            float areg[CPW];
#pragma unroll
            for (int i = 0; i < CPW; ++i)
                areg[i] = (lane < AD)
                        ? __ldg(&g_actions[(t * NTOT + nb + i) * AD + lane]) : 0.0f;
#pragma unroll
            for (int k = 0; k < AD; ++k) {
                ulonglong2 w01 = __ldg(&g_WaQ[(k * 2 + 0) * 32 + lane]);
                ulonglong2 w23 = __ldg(&g_WaQ[(k * 2 + 1) * 32 + lane]);
#pragma unroll
                for (int i = 0; i < CPW; ++i) {
                    float ak = __shfl_sync(0xFFFFFFFFu, areg[i], k);
                    ull ak2 = pk2(ak, ak);
                    fma2(accp[i][0], ak2, w01.x);
                    fma2(accp[i][1], ak2, w01.y);
                    fma2(accp[i][2], ak2, w23.x);
                    fma2(accp[i][3], ak2, w23.y);
                }
            }
        }

        __syncwarp();      // all reads of old sb rows done
        // tanh(acc + bb) + reward + store new beliefs (bias/Wr fetched from L1)
        {
            float bbl[3], bbh[3], wlo[3], whi[3];
#pragma unroll
            for (int q = 0; q < 3; ++q) {
                int h = lane + 64 * q;
                bbl[q] = __ldg(&bbv[h]);      bbh[q] = __ldg(&bbv[h + 32]);
                wlo[q] = __ldg(&Wr[h]);       whi[q] = __ldg(&Wr[h + 32]);
            }
            float bb6 = t6v ? __ldg(&bbv[192 + lane]) : 0.0f;
            float wr6 = t6v ? __ldg(&Wr[192 + lane]) : 0.0f;
#pragma unroll
            for (int i = 0; i < CPW; ++i) {
                float* row = &sb[(m0 + i) * HD];
#pragma unroll
                for (int q = 0; q < 3; ++q) {
                    float lo, hi;
                    upk2(lo, hi, accp[i][q]);
                    lo = tanh_fast(lo + bbl[q]); hi = tanh_fast(hi + bbh[q]);
                    rp[i] += lo * wlo[q] + hi * whi[q];
                    row[lane + 64 * q]      = lo;
                    row[lane + 64 * q + 32] = hi;
                }
                float t0, tz;
                upk2(t0, tz, accp[i][3]);
                float v6 = tanh_fast(t0 + bb6);
                rp[i] += v6 * wr6;           // wr6==0 for invalid lanes
                if (t6v) row[192 + lane] = v6;
            }
        }
        __syncwarp();      // new sb rows visible within warp

        // s_new = tanh(b_new @ Wz + bz)  (lane -> z), k-parity packed
        ull ac2p[CPW];
#pragma unroll
        for (int i = 0; i < CPW; ++i) ac2p[i] = pk2(bzz, 0.0f);
        for (int k2 = 0; k2 < HD / 2; ++k2) {
            ull wz2 = __ldg(&g_Wzp[k2 * 32 + lane]);   // 0 for lane>=30
#pragma unroll
            for (int i = 0; i < CPW; ++i) {
                ull bv2 = *reinterpret_cast<const ull*>(&sb[(m0 + i) * HD + 2 * k2]);
                fma2(ac2p[i], bv2, wz2);
            }
        }
        {
            float wrz = zval ? __ldg(&Wr[HD + lane]) : 0.0f;
#pragma unroll
            for (int i = 0; i < CPW; ++i) {
                float e, o;
                upk2(e, o, ac2p[i]);
                float sn = tanh_fast(e + o);
                rp[i] += sn * wrz;           // wrz==0 for invalid lanes
                sreg[i] = zval ? sn : 0.0f;
            }
        }
    }

    // warp-reduce rewards
#pragma unroll
    for (int off = 16; off; off >>= 1)
#pragma unroll
        for (int i = 0; i < CPW; ++i)
            rp[i] += __shfl_xor_sync(0xFFFFFFFFu, rp[i], off);
    if (lane == 0) {
        float brc = __ldg(&brv[0]);
#pragma unroll
        for (int i = 0; i < CPW; ++i)
            g_returns[nb + i] = rp[i] + (float)TT * brc;
    }
}

// per-batch top-100 (bitonic sort of 1024 packed keys) + mean/std refit
__global__ void select_kernel() {
    __shared__ unsigned long long key[1024];
    __shared__ int sidx[KTOP];
    const int b = blockIdx.x, tid = threadIdx.x;

    for (int i = tid; i < 1024; i += 256) {
        unsigned long long kk = 0ULL;
        if (i < CANDS) {
            unsigned u = __float_as_uint(g_returns[b * CANDS + i]);
            unsigned s = (u & 0x80000000u) ? ~u : (u | 0x80000000u);
            kk = ((unsigned long long)s << 32) | (unsigned)i;
        }
        key[i] = kk;
    }
    __syncthreads();
    for (int k = 2; k <= 1024; k <<= 1) {
        for (int j = k >> 1; j > 0; j >>= 1) {
            for (int i = tid; i < 1024; i += 256) {
                int ixj = i ^ j;
                if (ixj > i) {
                    unsigned long long a = key[i], c = key[ixj];
                    bool desc = ((i & k) == 0);
                    if (desc ? (a < c) : (a > c)) { key[i] = c; key[ixj] = a; }
                }
            }
            __syncthreads();
        }
    }
    if (tid < KTOP) sidx[tid] = (int)(key[tid] & 0xFFFFFFFFu);
    __syncthreads();

    if (tid < TT * AD) {
        int t = tid / AD, a = tid - t * AD;
        float sum = 0.0f;
        for (int r = 0; r < KTOP; ++r)
            sum += g_actions[(t * NTOT + b * CANDS + sidx[r]) * AD + a];
        float mean = sum * (1.0f / KTOP);
        float var = 0.0f;
        for (int r = 0; r < KTOP; ++r) {
            float d = g_actions[(t * NTOT + b * CANDS + sidx[r]) * AD + a] - mean;
            var += d * d;
        }
        var *= (1.0f / KTOP);
        int ms = (t * BBATCH + b) * AD + a;
        g_mean[ms] = mean;
        g_std[ms]  = sqrtf(var);
    }
}

__global__ void final_kernel(float* __restrict__ out) {
    int i = threadIdx.x;
    if (i < BBATCH * AD) out[i] = g_mean[i];   // t=0 slice is the first 96 entries
}

// ---------------- launch ----------------
extern "C" void kernel_launch(void* const* d_in, const int* in_sizes, int n_in,
                              void* d_out, int out_size) {
    (void)in_sizes; (void)n_in; (void)out_size;
    const float* belief = (const float*)d_in[0];
    const float* state  = (const float*)d_in[1];
    const float* Wb     = (const float*)d_in[2];
    const float* Ws     = (const float*)d_in[3];
    const float* Wa     = (const float*)d_in[4];
    const float* bb     = (const float*)d_in[5];
    const float* Wz     = (const float*)d_in[6];
    const float* bz     = (const float*)d_in[7];
    const float* Wr     = (const float*)d_in[8];
    const float* br     = (const float*)d_in[9];

    init_ms_kernel<<<(TT * BBATCH * AD + 255) / 256, 256>>>();
    {
        int total = 200 * 32 + 30 * 32 + 6 * 32 + 100 * 32;
        prep_kernel<<<(total + 255) / 256, 256>>>(Wb, Ws, Wa, Wz);
    }
    for (int it = 0; it < NITER; ++it) {
        // fold_in(key(42), it) = threefry(key=(0,42), count=(0,it)) on the host
        unsigned k0, k1;
        tf2x32(0u, 42u, 0u, (unsigned)it, k0, k1);
        gen_kernel<<<(NELEM + 255) / 256, 256>>>(k0, k1);
        rollout_kernel<<<NBLK, 256>>>(belief, state, bb, bz, Wr, br);
        select_kernel<<<BBATCH, 256>>>();
    }
    final_kernel<<<1, 128>>>((float*)d_out);
}

// round 13
// speedup vs baseline: 1.2540x; 1.2540x over previous
#include <cuda_runtime.h>
#include <cstdint>
#include <math.h>

// ---------------- problem constants ----------------
#define TT    12
#define NITER 10
#define CANDS 1000
#define KTOP  100
#define AD    6
#define BBATCH 16
#define HD    200
#define ZD    30
#define NTOT  (BBATCH * CANDS)     // 16000
#define NELEM (TT * NTOT * AD)     // 1152000
#define CPW   5                    // candidates per warp
#define MBLK  (8 * CPW)            // 40 candidates per block
#define NBLK  (NTOT / MBLK)        // 400 exactly; <= 3*148 -> one wave at 3 CTAs/SM

typedef unsigned long long ull;

// ---------------- device scratch (no allocations allowed) ----------------
__device__ float g_actions[NELEM];          // [T][16000][6]
__device__ float g_returns[NTOT];
__device__ float g_mean[TT * BBATCH * AD];  // [T][B][A]
__device__ float g_std [TT * BBATCH * AD];

// packed weights (prep_kernel fills once per launch)
// pair q=0..2: lane's columns (h0=lane+64q, h1=h0+32), both < 200
__device__ ull   g_Wbp[200 * 3 * 32];   // (Wb[k][h0], Wb[k][h1])
__device__ ull   g_Wsp[ 30 * 3 * 32];
__device__ ull   g_Wap[  6 * 3 * 32];
__device__ float g_Wb6[200 * 8];        // tail col h=192+lane, lane<8 (compact)
__device__ float g_Ws6[ 30 * 8];
__device__ float g_Wa6[  6 * 8];
__device__ ull   g_Wzp[100 * 32];       // (Wz[2k2][z], Wz[2k2+1][z]), 0 if z>=30

// ---------------- f32x2 helpers ----------------
__device__ __forceinline__ ull pk2(float a, float b) {
    ull r; asm("mov.b64 %0, {%1, %2};" : "=l"(r) : "f"(a), "f"(b)); return r;
}
__device__ __forceinline__ void upk2(float& a, float& b, ull v) {
    asm("mov.b64 {%0, %1}, %2;" : "=f"(a), "=f"(b) : "l"(v));
}
__device__ __forceinline__ void fma2(ull& d, ull a, ull b) {
    asm("fma.rn.f32x2 %0, %1, %2, %3;" : "=l"(d) : "l"(a), "l"(b), "l"(d));
}

// fast exact-identity tanh: 1 - 2/(e^{2x}+1); abs err ~1e-7, no NaN at +/-inf.
// Measured in R12: top-k selection and final output are bit-invariant to this.
__device__ __forceinline__ float tanh_fast(float x) {
    float e = __expf(2.0f * x);
    return 1.0f - __fdividef(2.0f, e + 1.0f);
}

// ---------------- Threefry-2x32-20 (exactly JAX's) ----------------
__host__ __device__ inline unsigned rotl32(unsigned v, int d) {
    return (v << d) | (v >> (32 - d));
}

__host__ __device__ inline void tf2x32(unsigned k0, unsigned k1,
                                       unsigned x0, unsigned x1,
                                       unsigned& o0, unsigned& o1) {
    unsigned ks0 = k0, ks1 = k1, ks2 = k0 ^ k1 ^ 0x1BD11BDAu;
    x0 += ks0; x1 += ks1;
#define TF_RND(r) { x0 += x1; x1 = rotl32(x1, (r)); x1 ^= x0; }
    TF_RND(13) TF_RND(15) TF_RND(26) TF_RND(6)
    x0 += ks1; x1 += ks2 + 1u;
    TF_RND(17) TF_RND(29) TF_RND(16) TF_RND(24)
    x0 += ks2; x1 += ks0 + 2u;
    TF_RND(13) TF_RND(15) TF_RND(26) TF_RND(6)
    x0 += ks0; x1 += ks1 + 3u;
    TF_RND(17) TF_RND(29) TF_RND(16) TF_RND(24)
    x0 += ks1; x1 += ks2 + 4u;
    TF_RND(13) TF_RND(15) TF_RND(26) TF_RND(6)
    x0 += ks2; x1 += ks0 + 5u;
#undef TF_RND
    o0 = x0; o1 = x1;
}

// XLA's f32 erf_inv (Giles polynomial), matching lax.erf_inv on GPU.
__device__ inline float xla_erfinvf(float x) {
    float w = -log1pf(-x * x);
    float p;
    if (w < 5.0f) {
        w -= 2.5f;
        p = 2.81022636e-08f;
        p = fmaf(p, w, 3.43273939e-07f);
        p = fmaf(p, w, -3.5233877e-06f);
        p = fmaf(p, w, -4.39150654e-06f);
        p = fmaf(p, w, 0.00021858087f);
        p = fmaf(p, w, -0.00125372503f);
        p = fmaf(p, w, -0.00417768164f);
        p = fmaf(p, w, 0.246640727f);
        p = fmaf(p, w, 1.50140941f);
    } else {
        w = sqrtf(w) - 3.0f;
        p = -0.000200214257f;
        p = fmaf(p, w, 0.000100950558f);
        p = fmaf(p, w, 0.00134934322f);
        p = fmaf(p, w, -0.00367342844f);
        p = fmaf(p, w, 0.00573950773f);
        p = fmaf(p, w, -0.0076224613f);
        p = fmaf(p, w, 0.00943887047f);
        p = fmaf(p, w, 1.00167406f);
        p = fmaf(p, w, 2.83297682f);
    }
    return p * x;
}

// bits -> uniform in [lo, 1) (JAX semantics) -> standard normal via erfinv
__device__ inline float bits_to_normal(unsigned bits) {
    float f = __uint_as_float((bits >> 9) | 0x3F800000u) - 1.0f;  // [0,1), exact
    float u = fmaf(f, 2.0f, -0.99999994f);
    u = fmaxf(-0.99999994f, u);
    return 1.41421356237f * xla_erfinvf(u);
}

// ---------------- kernels ----------------
__global__ void init_ms_kernel() {
    int i = blockIdx.x * blockDim.x + threadIdx.x;
    if (i < TT * BBATCH * AD) { g_mean[i] = 0.0f; g_std[i] = 1.0f; }
}

// Build packed/interleaved weight arrays. One thread per (k,lane) slot.
__global__ void prep_kernel(const float* __restrict__ Wb, const float* __restrict__ Ws,
                            const float* __restrict__ Wa, const float* __restrict__ Wz)
{
    int i = blockIdx.x * blockDim.x + threadIdx.x;
    if (i < 200 * 32) {
        int k = i >> 5, lane = i & 31;
        for (int q = 0; q < 3; ++q) {
            int h = lane + 64 * q;
            g_Wbp[(k * 3 + q) * 32 + lane] = pk2(Wb[k * HD + h], Wb[k * HD + h + 32]);
        }
        if (lane < 8) g_Wb6[k * 8 + lane] = Wb[k * HD + 192 + lane];
    }
    int j = i - 200 * 32;
    if (j >= 0 && j < 30 * 32) {
        int k = j >> 5, lane = j & 31;
        for (int q = 0; q < 3; ++q) {
            int h = lane + 64 * q;
            g_Wsp[(k * 3 + q) * 32 + lane] = pk2(Ws[k * HD + h], Ws[k * HD + h + 32]);
        }
        if (lane < 8) g_Ws6[k * 8 + lane] = Ws[k * HD + 192 + lane];
    }
    int l = j - 30 * 32;
    if (l >= 0 && l < 6 * 32) {
        int k = l >> 5, lane = l & 31;
        for (int q = 0; q < 3; ++q) {
            int h = lane + 64 * q;
            g_Wap[(k * 3 + q) * 32 + lane] = pk2(Wa[k * HD + h], Wa[k * HD + h + 32]);
        }
        if (lane < 8) g_Wa6[k * 8 + lane] = Wa[k * HD + 192 + lane];
    }
    int m = l - 6 * 32;
    if (m >= 0 && m < 100 * 32) {
        int k2 = m >> 5, z = m & 31;
        float e = (z < ZD) ? Wz[(2 * k2) * ZD + z] : 0.0f;
        float o = (z < ZD) ? Wz[(2 * k2 + 1) * ZD + z] : 0.0f;
        g_Wzp[m] = pk2(e, o);
    }
}

// Partitionable threefry, 32-bit output: bits[i] = o0 ^ o1 of
// threefry(key, counter=(hi=0, lo=i))
__global__ void gen_kernel(unsigned k0, unsigned k1) {
    int i = blockIdx.x * blockDim.x + threadIdx.x;
    if (i >= NELEM) return;
    unsigned o0, o1;
    tf2x32(k0, k1, 0u, (unsigned)i, o0, o1);
    float z = bits_to_normal(o0 ^ o1);
    int ms = (i / (CANDS * AD)) * AD + (i % AD);  // (t*B+b)*A + a
    g_actions[i] = fmaf(g_std[ms], z, g_mean[ms]);
}

// Fused 12-step rollout, f32x2-packed (64-bit weight loads), fast tanh.
// 3 CTAs/SM via CPW=5; beliefs in smem (warp-private rows);
// states/actions lane-distributed in registers.
// lane covers h-columns: pairs (lane+64q, lane+64q+32) q=0..2 + scalar 192+lane (lane<8)
__global__ __launch_bounds__(256, 3)
void rollout_kernel(const float* __restrict__ belief, const float* __restrict__ state,
                    const float* __restrict__ bbv, const float* __restrict__ bzv,
                    const float* __restrict__ Wr, const float* __restrict__ brv)
{
    __shared__ __align__(16) float sb[MBLK * HD];   // 32000 B static

    const int tid  = threadIdx.x;
    const int lane = tid & 31;
    const int warp = tid >> 5;
    const int nb   = blockIdx.x * MBLK + warp * CPW;   // first candidate of this warp

    // cooperative initial belief load (NBLK*MBLK == NTOT exactly; no clamps)
    for (int i = tid; i < MBLK * HD; i += 256) {
        int m = i / HD, h = i - m * HD;
        sb[i] = belief[((blockIdx.x * MBLK + m) / CANDS) * HD + h];
    }

    float sreg[CPW];   // lane z (<30) holds s[cand][z]
#pragma unroll
    for (int i = 0; i < CPW; ++i)
        sreg[i] = (lane < ZD) ? state[((nb + i) / CANDS) * ZD + lane] : 0.0f;

    const bool  t6v  = (lane < 8);
    const bool  zval = (lane < ZD);
    const float bzz  = zval ? __ldg(&bzv[lane]) : 0.0f;

    float rp[CPW];
#pragma unroll
    for (int i = 0; i < CPW; ++i) rp[i] = 0.0f;

    const int m0 = warp * CPW;
    __syncthreads();   // sb ready

    for (int t = 0; t < TT; ++t) {
        __syncthreads();   // keep warps converged on the weight stream (L1 reuse)

        ull   accp[CPW][3];
        float acc6[CPW];
#pragma unroll
        for (int i = 0; i < CPW; ++i) {
#pragma unroll
            for (int q = 0; q < 3; ++q) accp[i][q] = 0ULL;
            acc6[i] = 0.0f;
        }

        // b @ Wb   (K = 200)
#pragma unroll 2
        for (int k2 = 0; k2 < HD / 2; ++k2) {
            float2 bv[CPW];
#pragma unroll
            for (int i = 0; i < CPW; ++i)
                bv[i] = *reinterpret_cast<const float2*>(&sb[(m0 + i) * HD + 2 * k2]);
#pragma unroll
            for (int kk = 0; kk < 2; ++kk) {
                int k = 2 * k2 + kk;
                ull wq0 = __ldg(&g_Wbp[(k * 3 + 0) * 32 + lane]);
                ull wq1 = __ldg(&g_Wbp[(k * 3 + 1) * 32 + lane]);
                ull wq2 = __ldg(&g_Wbp[(k * 3 + 2) * 32 + lane]);
                float w6 = t6v ? __ldg(&g_Wb6[k * 8 + lane]) : 0.0f;
#pragma unroll
                for (int i = 0; i < CPW; ++i) {
                    float bk = kk ? bv[i].y : bv[i].x;
                    ull bk2 = pk2(bk, bk);
                    fma2(accp[i][0], bk2, wq0);
                    fma2(accp[i][1], bk2, wq1);
                    fma2(accp[i][2], bk2, wq2);
                    acc6[i] = fmaf(bk, w6, acc6[i]);
                }
            }
        }
        // s @ Ws   (K = 30)
        for (int k = 0; k < ZD; ++k) {
            ull wq0 = __ldg(&g_Wsp[(k * 3 + 0) * 32 + lane]);
            ull wq1 = __ldg(&g_Wsp[(k * 3 + 1) * 32 + lane]);
            ull wq2 = __ldg(&g_Wsp[(k * 3 + 2) * 32 + lane]);
            float w6 = t6v ? __ldg(&g_Ws6[k * 8 + lane]) : 0.0f;
#pragma unroll
            for (int i = 0; i < CPW; ++i) {
                float sk = __shfl_sync(0xFFFFFFFFu, sreg[i], k);
                ull sk2 = pk2(sk, sk);
                fma2(accp[i][0], sk2, wq0);
                fma2(accp[i][1], sk2, wq1);
                fma2(accp[i][2], sk2, wq2);
                acc6[i] = fmaf(sk, w6, acc6[i]);
            }
        }
        // a @ Wa   (K = 6) — actions loaded just-in-time
        {
            float areg[CPW];
#pragma unroll
            for (int i = 0; i < CPW; ++i)
                areg[i] = (lane < AD)
                        ? __ldg(&g_actions[(t * NTOT + nb + i) * AD + lane]) : 0.0f;
#pragma unroll
            for (int k = 0; k < AD; ++k) {
                ull wq0 = __ldg(&g_Wap[(k * 3 + 0) * 32 + lane]);
                ull wq1 = __ldg(&g_Wap[(k * 3 + 1) * 32 + lane]);
                ull wq2 = __ldg(&g_Wap[(k * 3 + 2) * 32 + lane]);
                float w6 = t6v ? __ldg(&g_Wa6[k * 8 + lane]) : 0.0f;
#pragma unroll
                for (int i = 0; i < CPW; ++i) {
                    float ak = __shfl_sync(0xFFFFFFFFu, areg[i], k);
                    ull ak2 = pk2(ak, ak);
                    fma2(accp[i][0], ak2, wq0);
                    fma2(accp[i][1], ak2, wq1);
                    fma2(accp[i][2], ak2, wq2);
                    acc6[i] = fmaf(ak, w6, acc6[i]);
                }
            }
        }

        __syncwarp();      // all reads of old sb rows done
        // tanh(acc + bb) + reward + store new beliefs (bias/Wr fetched from L1)
        {
            float bbl[3], bbh[3], wlo[3], whi[3];
#pragma unroll
            for (int q = 0; q < 3; ++q) {
                int h = lane + 64 * q;
                bbl[q] = __ldg(&bbv[h]);      bbh[q] = __ldg(&bbv[h + 32]);
                wlo[q] = __ldg(&Wr[h]);       whi[q] = __ldg(&Wr[h + 32]);
            }
            float bb6 = t6v ? __ldg(&bbv[192 + lane]) : 0.0f;
            float wr6 = t6v ? __ldg(&Wr[192 + lane]) : 0.0f;
#pragma unroll
            for (int i = 0; i < CPW; ++i) {
                float* row = &sb[(m0 + i) * HD];
#pragma unroll
                for (int q = 0; q < 3; ++q) {
                    float lo, hi;
                    upk2(lo, hi, accp[i][q]);
                    lo = tanh_fast(lo + bbl[q]); hi = tanh_fast(hi + bbh[q]);
                    rp[i] += lo * wlo[q] + hi * whi[q];
                    row[lane + 64 * q]      = lo;
                    row[lane + 64 * q + 32] = hi;
                }
                float v6 = tanh_fast(acc6[i] + bb6);
                rp[i] += v6 * wr6;           // wr6==0 for invalid lanes
                if (t6v) row[192 + lane] = v6;
            }
        }
        __syncwarp();      // new sb rows visible within warp

        // s_new = tanh(b_new @ Wz + bz)  (lane -> z), k-parity packed
        ull ac2p[CPW];
#pragma unroll
        for (int i = 0; i < CPW; ++i) ac2p[i] = pk2(bzz, 0.0f);
        for (int k2 = 0; k2 < HD / 2; ++k2) {
            ull wz2 = __ldg(&g_Wzp[k2 * 32 + lane]);   // 0 for lane>=30
#pragma unroll
            for (int i = 0; i < CPW; ++i) {
                ull bv2 = *reinterpret_cast<const ull*>(&sb[(m0 + i) * HD + 2 * k2]);
                fma2(ac2p[i], bv2, wz2);
            }
        }
        {
            float wrz = zval ? __ldg(&Wr[HD + lane]) : 0.0f;
#pragma unroll
            for (int i = 0; i < CPW; ++i) {
                float e, o;
                upk2(e, o, ac2p[i]);
                float sn = tanh_fast(e + o);
                rp[i] += sn * wrz;           // wrz==0 for invalid lanes
                sreg[i] = zval ? sn : 0.0f;
            }
        }
    }

    // warp-reduce rewards
#pragma unroll
    for (int off = 16; off; off >>= 1)
#pragma unroll
        for (int i = 0; i < CPW; ++i)
            rp[i] += __shfl_xor_sync(0xFFFFFFFFu, rp[i], off);
    if (lane == 0) {
        float brc = __ldg(&brv[0]);
#pragma unroll
        for (int i = 0; i < CPW; ++i)
            g_returns[nb + i] = rp[i] + (float)TT * brc;
    }
}

// per-batch top-100 (bitonic sort of 1024 packed keys) + mean/std refit
__global__ void select_kernel() {
    __shared__ unsigned long long key[1024];
    __shared__ int sidx[KTOP];
    const int b = blockIdx.x, tid = threadIdx.x;

    for (int i = tid; i < 1024; i += 256) {
        unsigned long long kk = 0ULL;
        if (i < CANDS) {
            unsigned u = __float_as_uint(g_returns[b * CANDS + i]);
            unsigned s = (u & 0x80000000u) ? ~u : (u | 0x80000000u);
            kk = ((unsigned long long)s << 32) | (unsigned)i;
        }
        key[i] = kk;
    }
    __syncthreads();
    for (int k = 2; k <= 1024; k <<= 1) {
        for (int j = k >> 1; j > 0; j >>= 1) {
            for (int i = tid; i < 1024; i += 256) {
                int ixj = i ^ j;
                if (ixj > i) {
                    unsigned long long a = key[i], c = key[ixj];
                    bool desc = ((i & k) == 0);
                    if (desc ? (a < c) : (a > c)) { key[i] = c; key[ixj] = a; }
                }
            }
            __syncthreads();
        }
    }
    if (tid < KTOP) sidx[tid] = (int)(key[tid] & 0xFFFFFFFFu);
    __syncthreads();

    if (tid < TT * AD) {
        int t = tid / AD, a = tid - t * AD;
        float sum = 0.0f;
        for (int r = 0; r < KTOP; ++r)
            sum += g_actions[(t * NTOT + b * CANDS + sidx[r]) * AD + a];
        float mean = sum * (1.0f / KTOP);
        float var = 0.0f;
        for (int r = 0; r < KTOP; ++r) {
            float d = g_actions[(t * NTOT + b * CANDS + sidx[r]) * AD + a] - mean;
            var += d * d;
        }
        var *= (1.0f / KTOP);
        int ms = (t * BBATCH + b) * AD + a;
        g_mean[ms] = mean;
        g_std[ms]  = sqrtf(var);
    }
}

__global__ void final_kernel(float* __restrict__ out) {
    int i = threadIdx.x;
    if (i < BBATCH * AD) out[i] = g_mean[i];   // t=0 slice is the first 96 entries
}

// ---------------- launch ----------------
extern "C" void kernel_launch(void* const* d_in, const int* in_sizes, int n_in,
                              void* d_out, int out_size) {
    (void)in_sizes; (void)n_in; (void)out_size;
    const float* belief = (const float*)d_in[0];
    const float* state  = (const float*)d_in[1];
    const float* Wb     = (const float*)d_in[2];
    const float* Ws     = (const float*)d_in[3];
    const float* Wa     = (const float*)d_in[4];
    const float* bb     = (const float*)d_in[5];
    const float* Wz     = (const float*)d_in[6];
    const float* bz     = (const float*)d_in[7];
    const float* Wr     = (const float*)d_in[8];
    const float* br     = (const float*)d_in[9];

    init_ms_kernel<<<(TT * BBATCH * AD + 255) / 256, 256>>>();
    {
        int total = 200 * 32 + 30 * 32 + 6 * 32 + 100 * 32;
        prep_kernel<<<(total + 255) / 256, 256>>>(Wb, Ws, Wa, Wz);
    }
    for (int it = 0; it < NITER; ++it) {
        // fold_in(key(42), it) = threefry(key=(0,42), count=(0,it)) on the host
        unsigned k0, k1;
        tf2x32(0u, 42u, 0u, (unsigned)it, k0, k1);
        gen_kernel<<<(NELEM + 255) / 256, 256>>>(k0, k1);
        rollout_kernel<<<NBLK, 256>>>(belief, state, bb, bz, Wr, br);
        select_kernel<<<BBATCH, 256>>>();
    }
    final_kernel<<<1, 128>>>((float*)d_out);
}